// round 16
// baseline (speedup 1.0000x reference)
#include <cuda_runtime.h>
#include <cuda_bf16.h>
#include <cstdint>

#define Nn 4096
#define NF 512
#define NH 64
#define H1 8
#define NC 16
#define WPR 128   // words per adjacency row (4096/32)

// ---------------- scratch (static device globals; no allocation) ----------------
__device__ __align__(16) unsigned g_adj[Nn * WPR];            // 2 MB bitmask
// g_ftb: MMA-staged layout: [h][jt(64)][f(64)][64 j, pair-permuted] bf16
__device__ __align__(16) __nv_bfloat16 g_ftb[H1 * NH * Nn];   // 4 MB
__device__ __align__(16) float g_wt[H1 * NH * NF];            // 1 MB  [h][f][k]
__device__ __align__(16) float2 g_EG1[H1 * Nn];               // (exp(s), exp(.2 s))
__device__ __align__(16) float2 g_FH1[H1 * Nn];               // (exp(nb), exp(.2 nb))
__device__ __align__(16) float g_h[Nn * (H1 * NH)];           // 8 MB
__device__ __align__(16) float g_feats2[Nn * NC];
__device__ __align__(16) float2 g_EG2[Nn];
__device__ __align__(16) float2 g_FH2[Nn];

// ---------------- helpers ----------------
__device__ __forceinline__ uint32_t tf32r(float f) {
    uint32_t r; asm("cvt.rna.tf32.f32 %0, %1;" : "=r"(r) : "f"(f)); return r;
}
__device__ __forceinline__ float tf32f(float f) {
    uint32_t r = tf32r(f); return __uint_as_float(r);
}
__device__ __forceinline__ void mma_tf32(float* c,
                                         uint32_t a0, uint32_t a1, uint32_t a2, uint32_t a3,
                                         uint32_t b0, uint32_t b1) {
    asm volatile(
        "mma.sync.aligned.m16n8k8.row.col.f32.tf32.tf32.f32 "
        "{%0,%1,%2,%3}, {%4,%5,%6,%7}, {%8,%9}, {%0,%1,%2,%3};"
        : "+f"(c[0]), "+f"(c[1]), "+f"(c[2]), "+f"(c[3])
        : "r"(a0), "r"(a1), "r"(a2), "r"(a3), "r"(b0), "r"(b1));
}
__device__ __forceinline__ void mma_bf16(float* c,
                                         uint32_t a0, uint32_t a1, uint32_t a2, uint32_t a3,
                                         uint32_t b0, uint32_t b1) {
    asm volatile(
        "mma.sync.aligned.m16n8k16.row.col.f32.bf16.bf16.f32 "
        "{%0,%1,%2,%3}, {%4,%5,%6,%7}, {%8,%9}, {%0,%1,%2,%3};"
        : "+f"(c[0]), "+f"(c[1]), "+f"(c[2]), "+f"(c[3])
        : "r"(a0), "r"(a1), "r"(a2), "r"(a3), "r"(b0), "r"(b1));
}
__device__ __forceinline__ uint32_t pack_bf16x2(float lo, float hi) {
    uint32_t d;
    asm("cvt.rn.bf16x2.f32 %0, %1, %2;" : "=r"(d) : "f"(hi), "f"(lo));
    return d;
}
__device__ __forceinline__ void cp16(void* dst, const void* src) {
    uint32_t d = (uint32_t)__cvta_generic_to_shared(dst);
    asm volatile("cp.async.cg.shared.global [%0], [%1], 16;" :: "r"(d), "l"(src) : "memory");
}
__device__ __forceinline__ void cp_commit() {
    asm volatile("cp.async.commit_group;" ::: "memory");
}
__device__ __forceinline__ void cp_wait_all() {
    asm volatile("cp.async.wait_group 0;" ::: "memory");
}
// bf16x2 AND-mask from 2 adjacent adjacency bits in t (bit0 -> low half, bit1 -> high)
__device__ __forceinline__ uint32_t bitmask2(unsigned t) {
    return (t & 1u) * 0xFFFFu + (t & 2u) * 0x7FFF8000u;
}

// ---------------- K1a: W1 transpose/round -> g_wt -------------------------------
__global__ void k_wt(const float* __restrict__ W1) {
    __shared__ float t[32][33];
    int idx = blockIdx.x;                  // 0..255
    int h = idx >> 5;
    int r = idx & 31;
    int kt = (r >> 1) * 32, ft = (r & 1) * 32;
    int x = threadIdx.x & 31, y = threadIdx.x >> 5;
    const float* src = W1 + (size_t)h * NF * NH;
#pragma unroll
    for (int rr = y; rr < 32; rr += 8)
        t[rr][x] = src[(size_t)(kt + rr) * NH + ft + x];
    __syncthreads();
    float* dst = g_wt + (size_t)h * NH * NF;
#pragma unroll
    for (int rr = y; rr < 32; rr += 8)
        dst[(size_t)(ft + rr) * NF + kt + x] = tf32f(t[x][rr]);
}

// ---------------- K1b: adjacency -> bitmask -------------------------------------
__global__ void k_adjbits(const int* __restrict__ adj) {
    int gw = blockIdx.x * 8 + (threadIdx.x >> 5);
    int lane = threadIdx.x & 31;
    int row = gw >> 2, q = gw & 3;
    const int* base = adj + (size_t)row * Nn + q * 1024;
    unsigned* wbase = g_adj + row * WPR + q * 32;
#pragma unroll 4
    for (int w = 0; w < 32; ++w) {
        unsigned m = __ballot_sync(0xffffffffu, base[w * 32 + lane] > 0);
        if (lane == 0) wbase[w] = m;
    }
}

// ---------------- K2: gemm1 (K=64 chunks) + fused ftb-permute + EG/FH ----------
__global__ void __launch_bounds__(256, 2) k_gemm1_mma(const float* __restrict__ x,
                                                      const float* __restrict__ as1,
                                                      const float* __restrict__ an1) {
    int h = blockIdx.y;
    int i0 = blockIdx.x * 128;
    int tid = threadIdx.x, wid = tid >> 5, lane = tid & 31;
    int gid = lane >> 2, tig = lane & 3;
    __shared__ float Xs[128][72];    // 288B rows; reused as ftb staging (9216 words)
    __shared__ float Wt_s[64][72];
    __shared__ __align__(16) float avs[64], nvs[64];

    if (tid < 64) { avs[tid] = as1[h * NH + tid]; nvs[tid] = an1[h * NH + tid]; }

    int r0 = wid * 16 + gid, r1 = r0 + 8;
    float c[8][4] = {};

    int srow = tid >> 1, shalf = tid & 1;
    int sf = tid >> 2, sq = tid & 3;
    const float* xsrc = x + (size_t)(i0 + srow) * NF + shalf * 32;
    const float* wsrc = g_wt + ((size_t)h * NH + sf) * NF + sq * 16;

    for (int kc = 0; kc < NF / 64; ++kc) {
        __syncthreads();
#pragma unroll
        for (int v = 0; v < 8; ++v) {
            float4 t = *(const float4*)(xsrc + kc * 64 + v * 4);
            t.x = tf32f(t.x); t.y = tf32f(t.y); t.z = tf32f(t.z); t.w = tf32f(t.w);
            *(float4*)&Xs[srow][shalf * 32 + v * 4] = t;
        }
#pragma unroll
        for (int v = 0; v < 4; ++v) {
            float4 w = *(const float4*)(wsrc + kc * 64 + v * 4);
            *(float4*)&Wt_s[sf][sq * 16 + v * 4] = w;
        }
        __syncthreads();
#pragma unroll
        for (int ks = 0; ks < 8; ++ks) {
            int k0 = ks * 8 + 2 * tig;
            float2 a02 = *(const float2*)&Xs[r0][k0];
            float2 a13 = *(const float2*)&Xs[r1][k0];
            uint32_t a0 = __float_as_uint(a02.x), a2 = __float_as_uint(a02.y);
            uint32_t a1 = __float_as_uint(a13.x), a3 = __float_as_uint(a13.y);
#pragma unroll
            for (int nt = 0; nt < 8; ++nt) {
                float2 b = *(const float2*)&Wt_s[nt * 8 + gid][k0];
                mma_tf32(c[nt], a0, a1, a2, a3, __float_as_uint(b.x), __float_as_uint(b.y));
            }
        }
    }

    // ---- epilogue A: EG/FH per row (registers only) ----
    float vs0 = 0.f, vn0 = 0.f, vs1 = 0.f, vn1 = 0.f;
#pragma unroll
    for (int nt = 0; nt < 8; ++nt) {
        int f0 = nt * 8 + 2 * tig;
        float2 av = *(const float2*)&avs[f0];
        float2 nv = *(const float2*)&nvs[f0];
        vs0 += c[nt][0] * av.x + c[nt][1] * av.y;
        vs1 += c[nt][2] * av.x + c[nt][3] * av.y;
        vn0 += c[nt][0] * nv.x + c[nt][1] * nv.y;
        vn1 += c[nt][2] * nv.x + c[nt][3] * nv.y;
    }
    vs0 += __shfl_xor_sync(0xffffffffu, vs0, 1); vs0 += __shfl_xor_sync(0xffffffffu, vs0, 2);
    vs1 += __shfl_xor_sync(0xffffffffu, vs1, 1); vs1 += __shfl_xor_sync(0xffffffffu, vs1, 2);
    vn0 += __shfl_xor_sync(0xffffffffu, vn0, 1); vn0 += __shfl_xor_sync(0xffffffffu, vn0, 2);
    vn1 += __shfl_xor_sync(0xffffffffu, vn1, 1); vn1 += __shfl_xor_sync(0xffffffffu, vn1, 2);
    if (tig == 0) {
        int gi0 = h * Nn + i0 + r0, gi1 = h * Nn + i0 + r1;
        g_EG1[gi0] = make_float2(__expf(vs0), __expf(0.2f * vs0));
        g_FH1[gi0] = make_float2(__expf(vn0), __expf(0.2f * vn0));
        g_EG1[gi1] = make_float2(__expf(vs1), __expf(0.2f * vs1));
        g_FH1[gi1] = make_float2(__expf(vn1), __expf(0.2f * vn1));
    }

    // ---- epilogue B: permuted bf16 tiles staged in smem, coalesced store ----
    __syncthreads();
    uint32_t* sst = (uint32_t*)&Xs[0][0];
    {
        int jl0 = r0 & 63, jl1 = r1 & 63;
        int q0 = (jl0 & 15) >> 1, q1 = (jl1 & 15) >> 1;
        int w0o = (jl0 >> 4) * 8 + (q0 < 4 ? 2 * q0 : 2 * (q0 - 4) + 1);
        int w1o = (jl1 >> 4) * 8 + (q1 < 4 ? 2 * q1 : 2 * (q1 - 4) + 1);
        uint32_t* tb = sst + (wid >> 2) * 2048;
        bool evengid = ((gid & 1) == 0);
#pragma unroll
        for (int nt = 0; nt < 8; ++nt) {
            float u0 = __shfl_down_sync(0xffffffffu, c[nt][0], 4);
            float u1 = __shfl_down_sync(0xffffffffu, c[nt][1], 4);
            float u2 = __shfl_down_sync(0xffffffffu, c[nt][2], 4);
            float u3 = __shfl_down_sync(0xffffffffu, c[nt][3], 4);
            if (evengid) {
                int f0 = nt * 8 + 2 * tig;
                tb[(f0 + 0) * 32 + w0o] = pack_bf16x2(c[nt][0], u0);
                tb[(f0 + 1) * 32 + w0o] = pack_bf16x2(c[nt][1], u1);
                tb[(f0 + 0) * 32 + w1o] = pack_bf16x2(c[nt][2], u2);
                tb[(f0 + 1) * 32 + w1o] = pack_bf16x2(c[nt][3], u3);
            }
        }
    }
    __syncthreads();
    {
        int jt0 = i0 >> 6;
#pragma unroll
        for (int r = 0; r < 4; ++r) {
            int idx = tid + r * 256;
            int tile = idx >> 9, within = idx & 511;
            uint4 v = ((const uint4*)sst)[idx];
            uint4* dst = (uint4*)((uint32_t*)g_ftb + ((size_t)(h * 64 + jt0 + tile)) * 2048);
            dst[within] = v;
        }
    }
}

// ---------------- K3: layer-1 attention, bf16 mma, 128-j chunks ----------------
__global__ void __launch_bounds__(256, 2) k_attn1_mma(const float* __restrict__ b1) {
    int h = blockIdx.y;
    int i0 = blockIdx.x * 128;
    int tid = threadIdx.x, wid = tid >> 5, lane = tid & 31;
    int gid = lane >> 2, tig = lane & 3;

    __shared__ __align__(16) __nv_bfloat16 Ft_s[2][2][64][80];  // 2 buf x 2 sub
    __shared__ __align__(16) float2 FHs[2][128];
    __shared__ float Rs[128];

    int r0 = wid * 16 + gid, r1 = r0 + 8;
    float2 eg0 = g_EG1[h * Nn + i0 + r0];
    float2 eg1 = g_EG1[h * Nn + i0 + r1];
    float c[9][4] = {};
    uint32_t bones = (gid == 0) ? 0x3F803F80u : 0u;   // ones-column B fragment

    const float2* fhsrc = g_FH1 + h * Nn;
    const uint4* adj0 = (const uint4*)(g_adj + (size_t)(i0 + r0) * WPR);
    const uint4* adj1 = (const uint4*)(g_adj + (size_t)(i0 + r1) * WPR);

    auto stage = [&](int jt2, int buf) {
        const char* fbase = (const char*)g_ftb + ((size_t)(h * 64 + jt2 * 2)) * 8192;
#pragma unroll
        for (int r = 0; r < 4; ++r) {
            int cidx = tid + r * 256;
            int sub = cidx >> 9, cin = cidx & 511;
            cp16(&Ft_s[buf][sub][cin >> 3][(cin & 7) * 8], fbase + cidx * 16);
        }
        if (tid < 64) cp16(&FHs[buf][tid * 2], fhsrc + jt2 * 128 + tid * 2);
        cp_commit();
    };

    uint4 a0n = adj0[0], a1n = adj1[0];
    stage(0, 0);
    for (int jt2 = 0; jt2 < Nn / 128; ++jt2) {
        int buf = jt2 & 1;
        cp_wait_all();
        __syncthreads();
        if (jt2 + 1 < Nn / 128) stage(jt2 + 1, buf ^ 1);

        uint4 ca0 = a0n, ca1 = a1n;
        if (jt2 + 1 < Nn / 128) { a0n = adj0[jt2 + 1]; a1n = adj1[jt2 + 1]; }

#pragma unroll
        for (int sub = 0; sub < 2; ++sub) {
            unsigned wa0 = sub ? ca0.z : ca0.x, wb0 = sub ? ca0.w : ca0.y;
            unsigned wa1 = sub ? ca1.z : ca1.x, wb1 = sub ? ca1.w : ca1.y;
            const char* fsbase = (const char*)&Ft_s[buf][sub][0][0];
            const float2* fhb = &FHs[buf][sub * 64];
#pragma unroll
            for (int ks = 0; ks < 4; ++ks) {
                int jb2 = ks * 16;
                unsigned sw0 = ((ks & 2) ? wb0 : wa0) >> ((ks & 1) * 16);
                unsigned sw1 = ((ks & 2) ? wb1 : wa1) >> ((ks & 1) * 16);
                int j0 = 2 * tig, j2 = j0 + 8;
                float4 fA = *(const float4*)&fhb[jb2 + j0];
                float4 fB = *(const float4*)&fhb[jb2 + j2];
                float p00 = fmaxf(eg0.x * fA.x, eg0.y * fA.y);
                float p01 = fmaxf(eg0.x * fA.z, eg0.y * fA.w);
                float p02 = fmaxf(eg0.x * fB.x, eg0.y * fB.y);
                float p03 = fmaxf(eg0.x * fB.z, eg0.y * fB.w);
                float p10 = fmaxf(eg1.x * fA.x, eg1.y * fA.y);
                float p11 = fmaxf(eg1.x * fA.z, eg1.y * fA.w);
                float p12 = fmaxf(eg1.x * fB.x, eg1.y * fB.y);
                float p13 = fmaxf(eg1.x * fB.z, eg1.y * fB.w);
                uint32_t a0 = pack_bf16x2(p00, p01) & bitmask2(sw0 >> j0);
                uint32_t a1 = pack_bf16x2(p10, p11) & bitmask2(sw1 >> j0);
                uint32_t a2 = pack_bf16x2(p02, p03) & bitmask2(sw0 >> j2);
                uint32_t a3 = pack_bf16x2(p12, p13) & bitmask2(sw1 >> j2);
#pragma unroll
                for (int nt = 0; nt < 8; ++nt) {
                    uint2 bb = *(const uint2*)(fsbase + (nt * 8 + gid) * 160 + ks * 32 + tig * 8);
                    mma_bf16(c[nt], a0, a1, a2, a3, bb.x, bb.y);
                }
                mma_bf16(c[8], a0, a1, a2, a3, bones, bones);   // rowsum column
            }
        }
    }
    if (tig == 0) { Rs[r0] = c[8][0]; Rs[r1] = c[8][2]; }
    __syncthreads();

    float inv0 = 1.0f / Rs[r0];
    float inv1 = 1.0f / Rs[r1];
    const float* bh = b1 + h * NH;
    float* d0 = g_h + (size_t)(i0 + r0) * (H1 * NH) + h * NH;
    float* d1 = g_h + (size_t)(i0 + r1) * (H1 * NH) + h * NH;
#pragma unroll
    for (int nt = 0; nt < 8; ++nt) {
        int cc = nt * 8 + 2 * tig;
        float2 bb = *(const float2*)(bh + cc);
        *(float2*)(d0 + cc) = make_float2(fmaxf(c[nt][0] * inv0 + bb.x, 0.f),
                                          fmaxf(c[nt][1] * inv0 + bb.y, 0.f));
        *(float2*)(d1 + cc) = make_float2(fmaxf(c[nt][2] * inv1 + bb.x, 0.f),
                                          fmaxf(c[nt][3] * inv1 + bb.y, 0.f));
    }
}

// ---------------- K4: feats2 = h @ W2 — warp per 2 rows ------------------------
__global__ void __launch_bounds__(256) k_gemm2(const float* __restrict__ W2,
                                               const float* __restrict__ as2,
                                               const float* __restrict__ an2) {
    __shared__ float Wt[NC][520];          // [f][k], padded row
    __shared__ __align__(16) float as_s[NC], an_s[NC];
    int tid = threadIdx.x;
    for (int u = tid; u < NF * NC; u += 256) {
        int k = u >> 4, f = u & 15;
        Wt[f][k] = W2[u];
    }
    if (tid < NC) { as_s[tid] = as2[tid]; an_s[tid] = an2[tid]; }
    __syncthreads();

    int wid = tid >> 5, lane = tid & 31;
    int row0 = blockIdx.x * 16 + wid * 2;
    float acc[2][NC] = {};
#pragma unroll
    for (int p = 0; p < 4; ++p) {
        float4 xv0 = *(const float4*)(g_h + (size_t)(row0 + 0) * NF + p * 128 + lane * 4);
        float4 xv1 = *(const float4*)(g_h + (size_t)(row0 + 1) * NF + p * 128 + lane * 4);
#pragma unroll
        for (int f = 0; f < NC; ++f) {
            float4 wv = *(const float4*)&Wt[f][p * 128 + lane * 4];   // 1 LDS / 8 FMA
            acc[0][f] += xv0.x * wv.x + xv0.y * wv.y + xv0.z * wv.z + xv0.w * wv.w;
            acc[1][f] += xv1.x * wv.x + xv1.y * wv.y + xv1.z * wv.z + xv1.w * wv.w;
        }
    }
#pragma unroll
    for (int rr = 0; rr < 2; ++rr)
#pragma unroll
        for (int f = 0; f < NC; ++f)
#pragma unroll
            for (int o = 16; o; o >>= 1)
                acc[rr][f] += __shfl_xor_sync(0xffffffffu, acc[rr][f], o);
    if (lane < 2) {
        int rr = lane, row = row0 + rr;
        float sv = 0.f, nv = 0.f;
#pragma unroll
        for (int f = 0; f < NC; ++f) { sv = fmaf(acc[rr][f], as_s[f], sv); nv = fmaf(acc[rr][f], an_s[f], nv); }
        float4* fo = (float4*)&g_feats2[(size_t)row * NC];
        fo[0] = make_float4(acc[rr][0], acc[rr][1], acc[rr][2], acc[rr][3]);
        fo[1] = make_float4(acc[rr][4], acc[rr][5], acc[rr][6], acc[rr][7]);
        fo[2] = make_float4(acc[rr][8], acc[rr][9], acc[rr][10], acc[rr][11]);
        fo[3] = make_float4(acc[rr][12], acc[rr][13], acc[rr][14], acc[rr][15]);
        g_EG2[row] = make_float2(__expf(sv), __expf(0.2f * sv));
        g_FH2[row] = make_float2(__expf(nv), __expf(0.2f * nv));
    }
}

// ---------------- K5: layer-2 attention + relu + log_softmax -------------------
__global__ void k_attn2(const float* __restrict__ b2, float* __restrict__ out) {
    int i0 = blockIdx.x * 32;
    int tid = threadIdx.x;
    __shared__ float Ps[64][36];
    __shared__ __align__(16) float Fs[64][16];
    __shared__ float2 fhs[64];
    __shared__ float RsP[32][8];
    int pr = tid >> 3, pj = tid & 7;
    int irow = i0 + pr;
    float2 eg = g_EG2[irow];
    const unsigned* bi = g_adj + (size_t)irow * WPR;
    int tx = tid & 15, tq = tid >> 4;
    float acc0 = 0.f, acc1 = 0.f, rs = 0.f;

    for (int jt = 0; jt < Nn / 64; ++jt) {
        __syncthreads();
        ((float4*)&Fs[0][0])[tid] = ((const float4*)(g_feats2 + (size_t)jt * 64 * NC))[tid];
        if (tid < 64) fhs[tid] = g_FH2[jt * 64 + tid];
        __syncthreads();
        unsigned w0 = bi[jt * 2], w1 = bi[jt * 2 + 1];
#pragma unroll
        for (int k = 0; k < 8; ++k) {
            int j = pj + k * 8;
            unsigned bit = (j < 32) ? ((w0 >> j) & 1u) : ((w1 >> (j - 32)) & 1u);
            float2 fh = fhs[j];
            float p = bit ? fmaxf(eg.x * fh.x, eg.y * fh.y) : 0.f;
            rs += p;
            Ps[j][pr] = p;
        }
        __syncthreads();
#pragma unroll 8
        for (int j = 0; j < 64; ++j) {
            float b = Fs[j][tx];
            acc0 = fmaf(Ps[j][tq * 2], b, acc0);
            acc1 = fmaf(Ps[j][tq * 2 + 1], b, acc1);
        }
    }
    __syncthreads();
    RsP[pr][pj] = rs;
    __syncthreads();
    float s0 = 0.f, s1 = 0.f;
#pragma unroll
    for (int k = 0; k < 8; ++k) { s0 += RsP[tq * 2][k]; s1 += RsP[tq * 2 + 1][k]; }
    float bb = b2[tx];
    float v0 = fmaxf(acc0 / s0 + bb, 0.f);
    float v1 = fmaxf(acc1 / s1 + bb, 0.f);
    float m0 = v0, m1 = v1;
#pragma unroll
    for (int o = 8; o; o >>= 1) {
        m0 = fmaxf(m0, __shfl_xor_sync(0xffffffffu, m0, o));
        m1 = fmaxf(m1, __shfl_xor_sync(0xffffffffu, m1, o));
    }
    float e0 = __expf(v0 - m0), e1 = __expf(v1 - m1);
#pragma unroll
    for (int o = 8; o; o >>= 1) {
        e0 += __shfl_xor_sync(0xffffffffu, e0, o);
        e1 += __shfl_xor_sync(0xffffffffu, e1, o);
    }
    out[(size_t)(i0 + tq * 2 + 0) * NC + tx] = v0 - (logf(e0) + m0);
    out[(size_t)(i0 + tq * 2 + 1) * NC + tx] = v1 - (logf(e1) + m1);
}

// ---------------- launcher ----------------
extern "C" void kernel_launch(void* const* d_in, const int* in_sizes, int n_in,
                              void* d_out, int out_size) {
    (void)in_sizes; (void)n_in; (void)out_size;
    const float* x   = (const float*)d_in[0];
    const int*   adj = (const int*)d_in[1];
    const float* W1  = (const float*)d_in[2];
    const float* b1  = (const float*)d_in[3];
    const float* as1 = (const float*)d_in[4];
    const float* an1 = (const float*)d_in[5];
    const float* W2  = (const float*)d_in[6];
    const float* b2  = (const float*)d_in[7];
    const float* as2 = (const float*)d_in[8];
    const float* an2 = (const float*)d_in[9];
    float* out = (float*)d_out;

    k_wt<<<256, 256>>>(W1);                                  // 1
    k_gemm1_mma<<<dim3(Nn / 128, H1), 256>>>(x, as1, an1);   // 2
    k_adjbits<<<2048, 256>>>(adj);                           // 3
    k_attn1_mma<<<dim3(Nn / 128, H1), 256>>>(b1);            // 4  <- profiled launch
    k_gemm2<<<Nn / 16, 256>>>(W2, as2, an2);                 // 5
    k_attn2<<<Nn / 32, 256>>>(b2, out);                      // 6
}

// round 17
// speedup vs baseline: 1.0852x; 1.0852x over previous
#include <cuda_runtime.h>
#include <cuda_bf16.h>
#include <cstdint>

#define Nn 4096
#define NF 512
#define NH 64
#define H1 8
#define NC 16
#define WPR 128   // words per adjacency row (4096/32)

// ---------------- scratch (static device globals; no allocation) ----------------
__device__ __align__(16) unsigned g_adj[Nn * WPR];            // 2 MB bitmask
// g_ftb: MMA-staged layout: [h][jt(64)][f(64)][64 j, pair-permuted] bf16
__device__ __align__(16) __nv_bfloat16 g_ftb[H1 * NH * Nn];   // 4 MB
__device__ __align__(16) float g_wt[H1 * NH * NF];            // 1 MB  [h][f][k]
__device__ __align__(16) float2 g_EG1[H1 * Nn];               // (exp(s), exp(.2 s))
__device__ __align__(16) float2 g_FH1[H1 * Nn];               // (exp(nb), exp(.2 nb))
__device__ __align__(16) float g_h[Nn * (H1 * NH)];           // 8 MB
__device__ __align__(16) float g_feats2[Nn * NC];
__device__ __align__(16) float2 g_EG2[Nn];
__device__ __align__(16) float2 g_FH2[Nn];

// ---------------- helpers ----------------
__device__ __forceinline__ uint32_t tf32r(float f) {
    uint32_t r; asm("cvt.rna.tf32.f32 %0, %1;" : "=r"(r) : "f"(f)); return r;
}
__device__ __forceinline__ float tf32f(float f) {
    uint32_t r = tf32r(f); return __uint_as_float(r);
}
__device__ __forceinline__ void mma_tf32(float* c,
                                         uint32_t a0, uint32_t a1, uint32_t a2, uint32_t a3,
                                         uint32_t b0, uint32_t b1) {
    asm volatile(
        "mma.sync.aligned.m16n8k8.row.col.f32.tf32.tf32.f32 "
        "{%0,%1,%2,%3}, {%4,%5,%6,%7}, {%8,%9}, {%0,%1,%2,%3};"
        : "+f"(c[0]), "+f"(c[1]), "+f"(c[2]), "+f"(c[3])
        : "r"(a0), "r"(a1), "r"(a2), "r"(a3), "r"(b0), "r"(b1));
}
__device__ __forceinline__ void mma_bf16(float* c,
                                         uint32_t a0, uint32_t a1, uint32_t a2, uint32_t a3,
                                         uint32_t b0, uint32_t b1) {
    asm volatile(
        "mma.sync.aligned.m16n8k16.row.col.f32.bf16.bf16.f32 "
        "{%0,%1,%2,%3}, {%4,%5,%6,%7}, {%8,%9}, {%0,%1,%2,%3};"
        : "+f"(c[0]), "+f"(c[1]), "+f"(c[2]), "+f"(c[3])
        : "r"(a0), "r"(a1), "r"(a2), "r"(a3), "r"(b0), "r"(b1));
}
__device__ __forceinline__ uint32_t pack_bf16x2(float lo, float hi) {
    uint32_t d;
    asm("cvt.rn.bf16x2.f32 %0, %1, %2;" : "=r"(d) : "f"(hi), "f"(lo));
    return d;
}
__device__ __forceinline__ void cp16(void* dst, const void* src) {
    uint32_t d = (uint32_t)__cvta_generic_to_shared(dst);
    asm volatile("cp.async.cg.shared.global [%0], [%1], 16;" :: "r"(d), "l"(src) : "memory");
}
__device__ __forceinline__ void cp_commit() {
    asm volatile("cp.async.commit_group;" ::: "memory");
}
__device__ __forceinline__ void cp_wait_all() {
    asm volatile("cp.async.wait_group 0;" ::: "memory");
}
// bf16x2 AND-mask from 2 adjacent adjacency bits in t (bit0 -> low half, bit1 -> high)
__device__ __forceinline__ uint32_t bitmask2(unsigned t) {
    return (t & 1u) * 0xFFFFu + (t & 2u) * 0x7FFF8000u;
}

// ---------------- K1: prep = adjacency bitmask + W1 transpose/round ------------
__global__ void k_prep(const int* __restrict__ adj, const float* __restrict__ W1) {
    __shared__ float t[32][33];
    if (blockIdx.x < 2048) {
        int gw = blockIdx.x * 8 + (threadIdx.x >> 5);
        int lane = threadIdx.x & 31;
        int row = gw >> 2, q = gw & 3;
        const int* base = adj + (size_t)row * Nn + q * 1024;
        unsigned* wbase = g_adj + row * WPR + q * 32;
#pragma unroll 4
        for (int w = 0; w < 32; ++w) {
            unsigned m = __ballot_sync(0xffffffffu, base[w * 32 + lane] > 0);
            if (lane == 0) wbase[w] = m;
        }
    } else {
        int idx = blockIdx.x - 2048;           // 0..255
        int h = idx >> 5;
        int r = idx & 31;
        int kt = (r >> 1) * 32, ft = (r & 1) * 32;
        int x = threadIdx.x & 31, y = threadIdx.x >> 5;
        const float* src = W1 + (size_t)h * NF * NH;
#pragma unroll
        for (int rr = y; rr < 32; rr += 8)
            t[rr][x] = src[(size_t)(kt + rr) * NH + ft + x];
        __syncthreads();
        float* dst = g_wt + (size_t)h * NH * NF;
#pragma unroll
        for (int rr = y; rr < 32; rr += 8)
            dst[(size_t)(ft + rr) * NF + kt + x] = tf32f(t[x][rr]);
    }
}

// ---------------- K2: gemm1 + fused ftb-permute (smem staged) + EG/FH ----------
__global__ void __launch_bounds__(256, 2) k_gemm1_mma(const float* __restrict__ x,
                                                      const float* __restrict__ as1,
                                                      const float* __restrict__ an1) {
    int h = blockIdx.y;
    int i0 = blockIdx.x * 128;
    int tid = threadIdx.x, wid = tid >> 5, lane = tid & 31;
    int gid = lane >> 2, tig = lane & 3;
    __shared__ float Xs[128][40];    // 160B rows; reused as ftb staging
    __shared__ float Wt_s[64][40];
    __shared__ __align__(16) float avs[64], nvs[64];

    if (tid < 64) { avs[tid] = as1[h * NH + tid]; nvs[tid] = an1[h * NH + tid]; }

    int r0 = wid * 16 + gid, r1 = r0 + 8;
    float c[8][4] = {};

    int srow = tid >> 1, shalf = tid & 1;
    int sf = tid >> 2, sq = tid & 3;
    const float* xsrc = x + (size_t)(i0 + srow) * NF + shalf * 16;
    const float* wsrc = g_wt + ((size_t)h * NH + sf) * NF + sq * 8;

    for (int kc = 0; kc < NF / 32; ++kc) {
        __syncthreads();
#pragma unroll
        for (int v = 0; v < 4; ++v) {
            float4 t = *(const float4*)(xsrc + kc * 32 + v * 4);
            t.x = tf32f(t.x); t.y = tf32f(t.y); t.z = tf32f(t.z); t.w = tf32f(t.w);
            *(float4*)&Xs[srow][shalf * 16 + v * 4] = t;
        }
        {
            float4 v0 = *(const float4*)(wsrc + kc * 32);
            float4 v1 = *(const float4*)(wsrc + kc * 32 + 4);
            *(float4*)&Wt_s[sf][sq * 8] = v0;
            *(float4*)&Wt_s[sf][sq * 8 + 4] = v1;
        }
        __syncthreads();
#pragma unroll
        for (int ks = 0; ks < 4; ++ks) {
            int k0 = ks * 8 + 2 * tig;
            float2 a02 = *(const float2*)&Xs[r0][k0];
            float2 a13 = *(const float2*)&Xs[r1][k0];
            uint32_t a0 = __float_as_uint(a02.x), a2 = __float_as_uint(a02.y);
            uint32_t a1 = __float_as_uint(a13.x), a3 = __float_as_uint(a13.y);
#pragma unroll
            for (int nt = 0; nt < 8; ++nt) {
                float2 b = *(const float2*)&Wt_s[nt * 8 + gid][k0];
                mma_tf32(c[nt], a0, a1, a2, a3, __float_as_uint(b.x), __float_as_uint(b.y));
            }
        }
    }

    // ---- epilogue A: EG/FH per row (registers only) ----
    float vs0 = 0.f, vn0 = 0.f, vs1 = 0.f, vn1 = 0.f;
#pragma unroll
    for (int nt = 0; nt < 8; ++nt) {
        int f0 = nt * 8 + 2 * tig;
        float2 av = *(const float2*)&avs[f0];
        float2 nv = *(const float2*)&nvs[f0];
        vs0 += c[nt][0] * av.x + c[nt][1] * av.y;
        vs1 += c[nt][2] * av.x + c[nt][3] * av.y;
        vn0 += c[nt][0] * nv.x + c[nt][1] * nv.y;
        vn1 += c[nt][2] * nv.x + c[nt][3] * nv.y;
    }
    vs0 += __shfl_xor_sync(0xffffffffu, vs0, 1); vs0 += __shfl_xor_sync(0xffffffffu, vs0, 2);
    vs1 += __shfl_xor_sync(0xffffffffu, vs1, 1); vs1 += __shfl_xor_sync(0xffffffffu, vs1, 2);
    vn0 += __shfl_xor_sync(0xffffffffu, vn0, 1); vn0 += __shfl_xor_sync(0xffffffffu, vn0, 2);
    vn1 += __shfl_xor_sync(0xffffffffu, vn1, 1); vn1 += __shfl_xor_sync(0xffffffffu, vn1, 2);
    if (tig == 0) {
        int gi0 = h * Nn + i0 + r0, gi1 = h * Nn + i0 + r1;
        g_EG1[gi0] = make_float2(__expf(vs0), __expf(0.2f * vs0));
        g_FH1[gi0] = make_float2(__expf(vn0), __expf(0.2f * vn0));
        g_EG1[gi1] = make_float2(__expf(vs1), __expf(0.2f * vs1));
        g_FH1[gi1] = make_float2(__expf(vn1), __expf(0.2f * vn1));
    }

    // ---- epilogue B: permuted bf16 tiles staged in smem, coalesced store ----
    __syncthreads();
    uint32_t* sst = (uint32_t*)&Xs[0][0];
    {
        int jl0 = r0 & 63, jl1 = r1 & 63;
        int q0 = (jl0 & 15) >> 1, q1 = (jl1 & 15) >> 1;
        int w0o = (jl0 >> 4) * 8 + (q0 < 4 ? 2 * q0 : 2 * (q0 - 4) + 1);
        int w1o = (jl1 >> 4) * 8 + (q1 < 4 ? 2 * q1 : 2 * (q1 - 4) + 1);
        uint32_t* tb = sst + (wid >> 2) * 2048;
        bool evengid = ((gid & 1) == 0);
#pragma unroll
        for (int nt = 0; nt < 8; ++nt) {
            float u0 = __shfl_down_sync(0xffffffffu, c[nt][0], 4);
            float u1 = __shfl_down_sync(0xffffffffu, c[nt][1], 4);
            float u2 = __shfl_down_sync(0xffffffffu, c[nt][2], 4);
            float u3 = __shfl_down_sync(0xffffffffu, c[nt][3], 4);
            if (evengid) {
                int f0 = nt * 8 + 2 * tig;
                tb[(f0 + 0) * 32 + w0o] = pack_bf16x2(c[nt][0], u0);
                tb[(f0 + 1) * 32 + w0o] = pack_bf16x2(c[nt][1], u1);
                tb[(f0 + 0) * 32 + w1o] = pack_bf16x2(c[nt][2], u2);
                tb[(f0 + 1) * 32 + w1o] = pack_bf16x2(c[nt][3], u3);
            }
        }
    }
    __syncthreads();
    {
        int jt0 = i0 >> 6;
#pragma unroll
        for (int r = 0; r < 4; ++r) {
            int idx = tid + r * 256;
            int tile = idx >> 9, within = idx & 511;
            uint4 v = ((const uint4*)sst)[idx];
            uint4* dst = (uint4*)((uint32_t*)g_ftb + ((size_t)(h * 64 + jt0 + tile)) * 2048);
            dst[within] = v;
        }
    }
}

// ---------------- K3: layer-1 attention, bf16 mma, 128-j chunks ----------------
__global__ void __launch_bounds__(256, 2) k_attn1_mma(const float* __restrict__ b1) {
    int h = blockIdx.y;
    int i0 = blockIdx.x * 128;
    int tid = threadIdx.x, wid = tid >> 5, lane = tid & 31;
    int gid = lane >> 2, tig = lane & 3;

    __shared__ __align__(16) __nv_bfloat16 Ft_s[2][2][64][80];  // 2 buf x 2 sub
    __shared__ __align__(16) float2 FHs[2][128];
    __shared__ float Rs[128];

    int r0 = wid * 16 + gid, r1 = r0 + 8;
    float2 eg0 = g_EG1[h * Nn + i0 + r0];
    float2 eg1 = g_EG1[h * Nn + i0 + r1];
    float c[9][4] = {};
    uint32_t bones = (gid == 0) ? 0x3F803F80u : 0u;   // ones-column B fragment

    const float2* fhsrc = g_FH1 + h * Nn;
    const uint4* adj0 = (const uint4*)(g_adj + (size_t)(i0 + r0) * WPR);
    const uint4* adj1 = (const uint4*)(g_adj + (size_t)(i0 + r1) * WPR);

    auto stage = [&](int jt2, int buf) {
        const char* fbase = (const char*)g_ftb + ((size_t)(h * 64 + jt2 * 2)) * 8192;
#pragma unroll
        for (int r = 0; r < 4; ++r) {
            int cidx = tid + r * 256;
            int sub = cidx >> 9, cin = cidx & 511;
            cp16(&Ft_s[buf][sub][cin >> 3][(cin & 7) * 8], fbase + cidx * 16);
        }
        if (tid < 64) cp16(&FHs[buf][tid * 2], fhsrc + jt2 * 128 + tid * 2);
        cp_commit();
    };

    uint4 a0n = adj0[0], a1n = adj1[0];
    stage(0, 0);
    for (int jt2 = 0; jt2 < Nn / 128; ++jt2) {
        int buf = jt2 & 1;
        cp_wait_all();
        __syncthreads();
        if (jt2 + 1 < Nn / 128) stage(jt2 + 1, buf ^ 1);

        uint4 ca0 = a0n, ca1 = a1n;
        if (jt2 + 1 < Nn / 128) { a0n = adj0[jt2 + 1]; a1n = adj1[jt2 + 1]; }

#pragma unroll
        for (int sub = 0; sub < 2; ++sub) {
            unsigned wa0 = sub ? ca0.z : ca0.x, wb0 = sub ? ca0.w : ca0.y;
            unsigned wa1 = sub ? ca1.z : ca1.x, wb1 = sub ? ca1.w : ca1.y;
            const char* fsbase = (const char*)&Ft_s[buf][sub][0][0];
            const float2* fhb = &FHs[buf][sub * 64];
#pragma unroll
            for (int ks = 0; ks < 4; ++ks) {
                int jb2 = ks * 16;
                unsigned sw0 = ((ks & 2) ? wb0 : wa0) >> ((ks & 1) * 16);
                unsigned sw1 = ((ks & 2) ? wb1 : wa1) >> ((ks & 1) * 16);
                int j0 = 2 * tig, j2 = j0 + 8;
                float4 fA = *(const float4*)&fhb[jb2 + j0];
                float4 fB = *(const float4*)&fhb[jb2 + j2];
                float p00 = fmaxf(eg0.x * fA.x, eg0.y * fA.y);
                float p01 = fmaxf(eg0.x * fA.z, eg0.y * fA.w);
                float p02 = fmaxf(eg0.x * fB.x, eg0.y * fB.y);
                float p03 = fmaxf(eg0.x * fB.z, eg0.y * fB.w);
                float p10 = fmaxf(eg1.x * fA.x, eg1.y * fA.y);
                float p11 = fmaxf(eg1.x * fA.z, eg1.y * fA.w);
                float p12 = fmaxf(eg1.x * fB.x, eg1.y * fB.y);
                float p13 = fmaxf(eg1.x * fB.z, eg1.y * fB.w);
                uint32_t a0 = pack_bf16x2(p00, p01) & bitmask2(sw0 >> j0);
                uint32_t a1 = pack_bf16x2(p10, p11) & bitmask2(sw1 >> j0);
                uint32_t a2 = pack_bf16x2(p02, p03) & bitmask2(sw0 >> j2);
                uint32_t a3 = pack_bf16x2(p12, p13) & bitmask2(sw1 >> j2);
#pragma unroll
                for (int nt = 0; nt < 8; ++nt) {
                    uint2 bb = *(const uint2*)(fsbase + (nt * 8 + gid) * 160 + ks * 32 + tig * 8);
                    mma_bf16(c[nt], a0, a1, a2, a3, bb.x, bb.y);
                }
                mma_bf16(c[8], a0, a1, a2, a3, bones, bones);   // rowsum column
            }
        }
    }
    if (tig == 0) { Rs[r0] = c[8][0]; Rs[r1] = c[8][2]; }
    __syncthreads();

    float inv0 = 1.0f / Rs[r0];
    float inv1 = 1.0f / Rs[r1];
    const float* bh = b1 + h * NH;
    float* d0 = g_h + (size_t)(i0 + r0) * (H1 * NH) + h * NH;
    float* d1 = g_h + (size_t)(i0 + r1) * (H1 * NH) + h * NH;
#pragma unroll
    for (int nt = 0; nt < 8; ++nt) {
        int cc = nt * 8 + 2 * tig;
        float2 bb = *(const float2*)(bh + cc);
        *(float2*)(d0 + cc) = make_float2(fmaxf(c[nt][0] * inv0 + bb.x, 0.f),
                                          fmaxf(c[nt][1] * inv0 + bb.y, 0.f));
        *(float2*)(d1 + cc) = make_float2(fmaxf(c[nt][2] * inv1 + bb.x, 0.f),
                                          fmaxf(c[nt][3] * inv1 + bb.y, 0.f));
    }
}

// ---------------- K4: feats2 = h @ W2 — warp per 2 rows, x prefetch ------------
__global__ void __launch_bounds__(256) k_gemm2(const float* __restrict__ W2,
                                               const float* __restrict__ as2,
                                               const float* __restrict__ an2) {
    __shared__ float Wt[NC][520];          // [f][k], padded row
    __shared__ __align__(16) float as_s[NC], an_s[NC];
    int tid = threadIdx.x;
    for (int u = tid; u < NF * NC; u += 256) {
        int k = u >> 4, f = u & 15;
        Wt[f][k] = W2[u];
    }
    if (tid < NC) { as_s[tid] = as2[tid]; an_s[tid] = an2[tid]; }
    __syncthreads();

    int wid = tid >> 5, lane = tid & 31;
    int row0 = blockIdx.x * 16 + wid * 2;
    const float* h0 = g_h + (size_t)(row0 + 0) * NF + lane * 4;
    const float* h1 = g_h + (size_t)(row0 + 1) * NF + lane * 4;
    float acc[2][NC] = {};
    float4 nx0 = *(const float4*)h0;       // prefetch p=0
    float4 nx1 = *(const float4*)h1;
#pragma unroll
    for (int p = 0; p < 4; ++p) {
        float4 xv0 = nx0, xv1 = nx1;
        if (p + 1 < 4) {                   // prefetch p+1 before compute (MLP=2)
            nx0 = *(const float4*)(h0 + (p + 1) * 128);
            nx1 = *(const float4*)(h1 + (p + 1) * 128);
        }
#pragma unroll
        for (int f = 0; f < NC; ++f) {
            float4 wv = *(const float4*)&Wt[f][p * 128 + lane * 4];   // 1 LDS / 8 FMA
            acc[0][f] += xv0.x * wv.x + xv0.y * wv.y + xv0.z * wv.z + xv0.w * wv.w;
            acc[1][f] += xv1.x * wv.x + xv1.y * wv.y + xv1.z * wv.z + xv1.w * wv.w;
        }
    }
#pragma unroll
    for (int rr = 0; rr < 2; ++rr)
#pragma unroll
        for (int f = 0; f < NC; ++f)
#pragma unroll
            for (int o = 16; o; o >>= 1)
                acc[rr][f] += __shfl_xor_sync(0xffffffffu, acc[rr][f], o);
    if (lane < 2) {
        int rr = lane, row = row0 + rr;
        float sv = 0.f, nv = 0.f;
#pragma unroll
        for (int f = 0; f < NC; ++f) { sv = fmaf(acc[rr][f], as_s[f], sv); nv = fmaf(acc[rr][f], an_s[f], nv); }
        float4* fo = (float4*)&g_feats2[(size_t)row * NC];
        fo[0] = make_float4(acc[rr][0], acc[rr][1], acc[rr][2], acc[rr][3]);
        fo[1] = make_float4(acc[rr][4], acc[rr][5], acc[rr][6], acc[rr][7]);
        fo[2] = make_float4(acc[rr][8], acc[rr][9], acc[rr][10], acc[rr][11]);
        fo[3] = make_float4(acc[rr][12], acc[rr][13], acc[rr][14], acc[rr][15]);
        g_EG2[row] = make_float2(__expf(sv), __expf(0.2f * sv));
        g_FH2[row] = make_float2(__expf(nv), __expf(0.2f * nv));
    }
}

// ---------------- K5: layer-2 attention + relu + log_softmax -------------------
__global__ void k_attn2(const float* __restrict__ b2, float* __restrict__ out) {
    int i0 = blockIdx.x * 32;
    int tid = threadIdx.x;
    __shared__ float Ps[64][36];
    __shared__ __align__(16) float Fs[64][16];
    __shared__ float2 fhs[64];
    __shared__ float RsP[32][8];
    int pr = tid >> 3, pj = tid & 7;
    int irow = i0 + pr;
    float2 eg = g_EG2[irow];
    const unsigned* bi = g_adj + (size_t)irow * WPR;
    int tx = tid & 15, tq = tid >> 4;
    float acc0 = 0.f, acc1 = 0.f, rs = 0.f;

    for (int jt = 0; jt < Nn / 64; ++jt) {
        __syncthreads();
        ((float4*)&Fs[0][0])[tid] = ((const float4*)(g_feats2 + (size_t)jt * 64 * NC))[tid];
        if (tid < 64) fhs[tid] = g_FH2[jt * 64 + tid];
        __syncthreads();
        unsigned w0 = bi[jt * 2], w1 = bi[jt * 2 + 1];
#pragma unroll
        for (int k = 0; k < 8; ++k) {
            int j = pj + k * 8;
            unsigned bit = (j < 32) ? ((w0 >> j) & 1u) : ((w1 >> (j - 32)) & 1u);
            float2 fh = fhs[j];
            float p = bit ? fmaxf(eg.x * fh.x, eg.y * fh.y) : 0.f;
            rs += p;
            Ps[j][pr] = p;
        }
        __syncthreads();
#pragma unroll 8
        for (int j = 0; j < 64; ++j) {
            float b = Fs[j][tx];
            acc0 = fmaf(Ps[j][tq * 2], b, acc0);
            acc1 = fmaf(Ps[j][tq * 2 + 1], b, acc1);
        }
    }
    __syncthreads();
    RsP[pr][pj] = rs;
    __syncthreads();
    float s0 = 0.f, s1 = 0.f;
#pragma unroll
    for (int k = 0; k < 8; ++k) { s0 += RsP[tq * 2][k]; s1 += RsP[tq * 2 + 1][k]; }
    float bb = b2[tx];
    float v0 = fmaxf(acc0 / s0 + bb, 0.f);
    float v1 = fmaxf(acc1 / s1 + bb, 0.f);
    float m0 = v0, m1 = v1;
#pragma unroll
    for (int o = 8; o; o >>= 1) {
        m0 = fmaxf(m0, __shfl_xor_sync(0xffffffffu, m0, o));
        m1 = fmaxf(m1, __shfl_xor_sync(0xffffffffu, m1, o));
    }
    float e0 = __expf(v0 - m0), e1 = __expf(v1 - m1);
#pragma unroll
    for (int o = 8; o; o >>= 1) {
        e0 += __shfl_xor_sync(0xffffffffu, e0, o);
        e1 += __shfl_xor_sync(0xffffffffu, e1, o);
    }
    out[(size_t)(i0 + tq * 2 + 0) * NC + tx] = v0 - (logf(e0) + m0);
    out[(size_t)(i0 + tq * 2 + 1) * NC + tx] = v1 - (logf(e1) + m1);
}

// ---------------- launcher ----------------
extern "C" void kernel_launch(void* const* d_in, const int* in_sizes, int n_in,
                              void* d_out, int out_size) {
    (void)in_sizes; (void)n_in; (void)out_size;
    const float* x   = (const float*)d_in[0];
    const int*   adj = (const int*)d_in[1];
    const float* W1  = (const float*)d_in[2];
    const float* b1  = (const float*)d_in[3];
    const float* as1 = (const float*)d_in[4];
    const float* an1 = (const float*)d_in[5];
    const float* W2  = (const float*)d_in[6];
    const float* b2  = (const float*)d_in[7];
    const float* as2 = (const float*)d_in[8];
    const float* an2 = (const float*)d_in[9];
    float* out = (float*)d_out;

    k_prep<<<2048 + 256, 256>>>(adj, W1);                    // 1
    k_gemm1_mma<<<dim3(Nn / 128, H1), 256>>>(x, as1, an1);   // 2 (ftb + EG/FH fused)
    k_attn1_mma<<<dim3(Nn / 128, H1), 256>>>(b1);            // 3
    k_gemm2<<<Nn / 16, 256>>>(W2, as2, an2);                 // 4
    k_attn2<<<Nn / 32, 256>>>(b2, out);                      // 5
}